// round 11
// baseline (speedup 1.0000x reference)
#include <cuda_runtime.h>
#include <cstdint>

#define B_SZ 2048
#define T_SZ 256
#define IN_SZ 65
#define H_SZ 64
#define G_SZ 256           // 4*H
#define BR 16              // batch rows per recurrent block
#define NP 8               // row pairs per recurrent block
#define PST 10             // ull stride per k-row in hsbuf
#define NPAIR (B_SZ / 2)   // 1024 row pairs total
#define NTH1 512
#define NTH2 512

typedef unsigned long long ull;

// 537 MB device scratch for the precomputed input projections:
// xg_scratch[(pair*T + t)*256 + gate] = f32x2(row 2p, row 2p+1) pre-activation (incl. biases)
__device__ ull xg_scratch[(size_t)NPAIR * T_SZ * G_SZ];

__device__ __forceinline__ ull ffma2(ull a, ull b, ull c) {
    ull d;
    asm("fma.rn.f32x2 %0, %1, %2, %3;" : "=l"(d) : "l"(a), "l"(b), "l"(c));
    return d;
}
__device__ __forceinline__ ull fadd2(ull a, ull b) {
    ull d;
    asm("add.rn.f32x2 %0, %1, %2;" : "=l"(d) : "l"(a), "l"(b));
    return d;
}
__device__ __forceinline__ ull fdup(float v) {
    ull d;
    asm("mov.b64 %0, {%1, %1};" : "=l"(d) : "f"(v));
    return d;
}
__device__ __forceinline__ ull fpack(float lo, float hi) {
    ull d;
    asm("mov.b64 %0, {%1, %2};" : "=l"(d) : "f"(lo), "f"(hi));
    return d;
}
__device__ __forceinline__ void funpack(ull v, float& lo, float& hi) {
    asm("mov.b64 {%0, %1}, %2;" : "=f"(lo), "=f"(hi) : "l"(v));
}
__device__ __forceinline__ float ex2f(float x) {
    float y; asm("ex2.approx.f32 %0, %1;" : "=f"(y) : "f"(x)); return y;
}
__device__ __forceinline__ float rcpf(float x) {
    float y; asm("rcp.approx.f32 %0, %1;" : "=f"(y) : "f"(x)); return y;
}
__device__ __forceinline__ float sigf(float x) {
    return rcpf(1.0f + ex2f(-1.4426950408889634f * x));
}
__device__ __forceinline__ float tanhf_(float x) {
    return fmaf(2.0f, rcpf(1.0f + ex2f(-2.8853900817779268f * x)), -1.0f);
}

// ============================================================================
// Pass 1: xg = x @ Wih^T + (bih + bhh), packed as row-pairs.
// Block = (pair, t-half of 128). Two 64-t chunks staged in smem as [k][item].
// ============================================================================
__global__ __launch_bounds__(NTH1, 1)
void xproj_kernel(const float* __restrict__ x,
                  const float* __restrict__ Wih,
                  const float* __restrict__ bih,
                  const float* __restrict__ bhh) {
    __shared__ ull xs[IN_SZ * 64];   // [k][item]

    const int tid = threadIdx.x;
    const int pr = blockIdx.x >> 1;
    const int t0base = (blockIdx.x & 1) * 128;
    const int j = tid & 255;         // owned gate column
    const int half = tid >> 8;       // item half (0: items 0-31, 1: 32-63)

    float w_[IN_SZ];
#pragma unroll
    for (int k = 0; k < IN_SZ; ++k) w_[k] = Wih[j * IN_SZ + k];
    const ull binit = fdup(bih[j] + bhh[j]);

    const float* xlo = x + (size_t)(2 * pr) * T_SZ * IN_SZ;
    const float* xhi = x + (size_t)(2 * pr + 1) * T_SZ * IN_SZ;

#pragma unroll 1
    for (int c = 0; c < 2; ++c) {
        const int t0 = t0base + c * 64;
        const float* lo = xlo + (size_t)t0 * IN_SZ;
        const float* hi = xhi + (size_t)t0 * IN_SZ;
        if (c) __syncthreads();       // protect xs reuse
        for (int idx = tid; idx < 64 * IN_SZ; idx += NTH1) {
            int i = idx / IN_SZ;
            int k = idx - i * IN_SZ;
            xs[k * 64 + i] = fpack(lo[idx], hi[idx]);
        }
        __syncthreads();

        const int ibase = half * 32;
#pragma unroll 1
        for (int g = 0; g < 8; ++g) {
            const int i0 = ibase + g * 4;
            ull a0 = binit, a1 = binit, a2 = binit, a3 = binit;
            const ull* sp = xs + i0;
#pragma unroll
            for (int k = 0; k < IN_SZ; ++k) {
                const ull wd = fdup(w_[k]);
                ulonglong2 p01 = *(const ulonglong2*)(sp);
                ulonglong2 p23 = *(const ulonglong2*)(sp + 2);
                sp += 64;
                a0 = ffma2(wd, p01.x, a0); a1 = ffma2(wd, p01.y, a1);
                a2 = ffma2(wd, p23.x, a2); a3 = ffma2(wd, p23.y, a3);
            }
            ull* dst = xg_scratch + ((size_t)pr * T_SZ + t0 + i0) * G_SZ + j;
            dst[0 * G_SZ] = a0; dst[1 * G_SZ] = a1;
            dst[2 * G_SZ] = a2; dst[3 * G_SZ] = a3;
        }
    }
}

// ============================================================================
// Pass 2: recurrence. h-MAC (64 k) + update only; xg(t) streamed from GMEM.
// MAC: thread = (gate j, row-half rh) -> 4 row-pairs. 4 warps/SMSP.
// Update: thread = (unit uu, pair p).
// ============================================================================
__global__ __launch_bounds__(NTH2, 1)
void lstm_rec_kernel(const float* __restrict__ Whh,
                     const float* __restrict__ fcW,
                     const float* __restrict__ fcb,
                     float* __restrict__ out) {
    __shared__ ull hsbuf[H_SZ * PST];   // h row-pairs [k][pair]
    __shared__ ull hg[NP * G_SZ];       // h-part gates [pair][gate]

    const int tid = threadIdx.x;
    const int pb = blockIdx.x * NP;     // global pair base
    const int b0 = blockIdx.x * BR;
    const int j  = tid & 255;           // owned gate column (MAC role)
    const int rh = tid >> 8;            // row-half 0/1 (MAC role)

    float w_[H_SZ];
#pragma unroll
    for (int k = 0; k < H_SZ; ++k) w_[k] = Whh[j * H_SZ + k];

    for (int i = tid; i < H_SZ * PST; i += NTH2) hsbuf[i] = 0ULL;

    // update role: unit uu, pair p
    const int uu = tid & 63;
    const int p  = (tid >> 6) & 7;
    float cL = 0.f, cH = 0.f;
    const ull* xgp_base = xg_scratch + (size_t)(pb + p) * T_SZ * G_SZ + uu;

    __syncthreads();

    for (int t = 0; t < T_SZ; ++t) {
        // ---- prefetch xg(t): issued before the MAC, consumed in phase B ----
        const ull* xgp = xgp_base + (size_t)t * G_SZ;
        const ull xI = xgp[0];
        const ull xF = xgp[64];
        const ull xG = xgp[128];
        const ull xO = xgp[192];

        // ===== phase A: h-MAC(t) — all 512 threads =====
        {
            ull a0 = 0, a1 = 0, a2 = 0, a3 = 0;
            const ull* sp = hsbuf + rh * 4;
#pragma unroll
            for (int k = 0; k < H_SZ; ++k) {
                const ull wd = fdup(w_[k]);
                ulonglong2 p01 = *(const ulonglong2*)(sp);
                ulonglong2 p23 = *(const ulonglong2*)(sp + 2);
                sp += PST;
                a0 = ffma2(wd, p01.x, a0); a1 = ffma2(wd, p01.y, a1);
                a2 = ffma2(wd, p23.x, a2); a3 = ffma2(wd, p23.y, a3);
            }
            ull* g = hg + rh * 4 * G_SZ + j;
            g[0 * G_SZ] = a0; g[1 * G_SZ] = a1;
            g[2 * G_SZ] = a2; g[3 * G_SZ] = a3;
        }
        __syncthreads();

        // ===== phase B: update(t) — all 512 threads, one (unit, pair) each =====
        {
            const ull* gh = hg + p * G_SZ;
            ull sI = fadd2(gh[uu],        xI);
            ull sF = fadd2(gh[64 + uu],   xF);
            ull sG = fadd2(gh[128 + uu],  xG);
            ull sO = fadd2(gh[192 + uu],  xO);
            float iL, iH, fL, fH, gL, gH, oL, oH;
            funpack(sI, iL, iH); funpack(sF, fL, fH);
            funpack(sG, gL, gH); funpack(sO, oL, oH);

            float iv = sigf(iL);
            float fv = sigf(fL);
            float gv = tanhf_(gL);
            float ov = sigf(oL);
            cL = fv * cL + iv * gv;
            float hLo = ov * tanhf_(cL);

            iv = sigf(iH);
            fv = sigf(fH);
            gv = tanhf_(gH);
            ov = sigf(oH);
            cH = fv * cH + iv * gv;
            float hHi = ov * tanhf_(cH);

            hsbuf[uu * PST + p] = fpack(hLo, hHi);
        }
        __syncthreads();
    }

    // ---- final FC head: out[b][o] = sigmoid(h . fcW[o] + fcb[o]) ----
    if (tid < BR * 7) {
        int r = tid / 7;
        int o = tid - r * 7;
        float s = fcb[o];
        const float* wrow = fcW + o * H_SZ;
#pragma unroll 8
        for (int u = 0; u < H_SZ; ++u) {
            float lo, hi;
            funpack(hsbuf[u * PST + (r >> 1)], lo, hi);
            s += wrow[u] * ((r & 1) ? hi : lo);
        }
        out[(size_t)(b0 + r) * 7 + o] = sigf(s);
    }
}

extern "C" void kernel_launch(void* const* d_in, const int* in_sizes, int n_in,
                              void* d_out, int out_size) {
    const float* x    = (const float*)d_in[0];
    const float* Wih  = (const float*)d_in[1];
    const float* Whh  = (const float*)d_in[2];
    const float* bih  = (const float*)d_in[3];
    const float* bhh  = (const float*)d_in[4];
    const float* fcW  = (const float*)d_in[5];
    const float* fcb  = (const float*)d_in[6];
    float* out = (float*)d_out;

    xproj_kernel<<<NPAIR * 2, NTH1>>>(x, Wih, bih, bhh);
    lstm_rec_kernel<<<B_SZ / BR, NTH2>>>(Whh, fcW, fcb, out);
}

// round 13
// speedup vs baseline: 2.7762x; 2.7762x over previous
#include <cuda_runtime.h>
#include <cuda_bf16.h>
#include <cstdint>

#define B_SZ 2048
#define T_SZ 256
#define IN_SZ 65
#define H_SZ 64
#define BR 16
#define NTH 256

typedef unsigned int u32;

// ---- smem layout (bytes) ----
#define AST 272                          // A row stride: 136 bf16 (16B-mult, LDSM conflict-free)
#define BST 272                          // hx row stride
#define OFF_AH 0                         // A hi  [256][AST]
#define OFF_AL (OFF_AH + 256 * AST)      // 69632: A lo
#define OFF_B  (OFF_AL + 256 * AST)      // 139264: hx [par][split][16][BST]
#define BSECT  (16 * BST)                // 4352
#define OFF_X64 (OFF_B + 4 * BSECT)      // 156672: x64 [par][16] float
#define OFF_HFIN (OFF_X64 + 2 * 16 * 4)  // 156800: hfin [16][68] float
#define SMEM_TOTAL (OFF_HFIN + 16 * 68 * 4)  // 161152

__device__ __forceinline__ u32 smem_u32(const void* p) {
    u32 a;
    asm("{ .reg .u64 t; cvta.to.shared.u64 t, %1; cvt.u32.u64 %0, t; }" : "=r"(a) : "l"(p));
    return a;
}
__device__ __forceinline__ void ldsm4(u32& r0, u32& r1, u32& r2, u32& r3, u32 addr) {
    asm volatile("ldmatrix.sync.aligned.m8n8.x4.shared.b16 {%0,%1,%2,%3}, [%4];"
                 : "=r"(r0), "=r"(r1), "=r"(r2), "=r"(r3) : "r"(addr));
}
__device__ __forceinline__ void mma16816(float* d, const u32* a, u32 b0, u32 b1) {
    asm volatile("mma.sync.aligned.m16n8k16.row.col.f32.bf16.bf16.f32 "
                 "{%0,%1,%2,%3}, {%4,%5,%6,%7}, {%8,%9}, {%0,%1,%2,%3};"
                 : "+f"(d[0]), "+f"(d[1]), "+f"(d[2]), "+f"(d[3])
                 : "r"(a[0]), "r"(a[1]), "r"(a[2]), "r"(a[3]), "r"(b0), "r"(b1));
}
__device__ __forceinline__ float ex2f(float x) { float y; asm("ex2.approx.f32 %0, %1;" : "=f"(y) : "f"(x)); return y; }
__device__ __forceinline__ float rcpf(float x) { float y; asm("rcp.approx.f32 %0, %1;" : "=f"(y) : "f"(x)); return y; }
__device__ __forceinline__ float sigf(float x) { return rcpf(1.0f + ex2f(-1.4426950408889634f * x)); }
__device__ __forceinline__ float tanhf_(float x) { return fmaf(2.0f, rcpf(1.0f + ex2f(-2.8853900817779268f * x)), -1.0f); }

__global__ __launch_bounds__(NTH, 1)
void lstm_mma_kernel(const float* __restrict__ x,
                     const float* __restrict__ Wih,
                     const float* __restrict__ Whh,
                     const float* __restrict__ bih,
                     const float* __restrict__ bhh,
                     const float* __restrict__ fcW,
                     const float* __restrict__ fcb,
                     float* __restrict__ out) {
    extern __shared__ char sm[];
    const u32 smb = smem_u32(sm);
    const int tid = threadIdx.x;
    const int wid = tid >> 5;
    const int lane = tid & 31;
    const int b0 = blockIdx.x * BR;

    // ---- one-time: W -> A tiles (split bf16). A row g, col k: k<64 = Whh, 64..127 = Wih[:,0:64]
    for (int idx = tid; idx < 256 * 128; idx += NTH) {
        int g = idx >> 7, k = idx & 127;
        float v = (k < 64) ? Whh[g * 64 + k] : Wih[g * 65 + (k - 64)];
        __nv_bfloat16 hi = __float2bfloat16(v);
        __nv_bfloat16 lo = __float2bfloat16(v - __bfloat162float(hi));
        *(__nv_bfloat16*)(sm + OFF_AH + g * AST + k * 2) = hi;
        *(__nv_bfloat16*)(sm + OFF_AL + g * AST + k * 2) = lo;
    }
    // zero hx buffers (h(-1)=0, padding) + x64
    for (int idx = tid; idx < (4 * BSECT) / 4; idx += NTH) ((u32*)(sm + OFF_B))[idx] = 0;
    if (tid < 32) ((float*)(sm + OFF_X64))[tid] = 0.0f;

    // ---- x-stream slots: 16 rows x 65 feats = 1040 -> 5 slots/thread
    const float* xptr[5]; int xn[5], xf[5]; bool xok[5];
#pragma unroll
    for (int m = 0; m < 5; ++m) {
        int idx = tid + m * NTH;
        xok[m] = idx < 16 * IN_SZ;
        int n = xok[m] ? idx / IN_SZ : 0;
        int f = xok[m] ? idx - n * IN_SZ : 0;
        xn[m] = n; xf[m] = f;
        xptr[m] = x + ((size_t)(b0 + n) * T_SZ) * IN_SZ + f;
    }
    __syncthreads();
    // x(0) -> parity 0
#pragma unroll
    for (int m = 0; m < 5; ++m) {
        if (xok[m]) {
            float v = *xptr[m];
            xptr[m] += IN_SZ;
            if (xf[m] == 64) ((float*)(sm + OFF_X64))[xn[m]] = v;
            else {
                __nv_bfloat16 hi = __float2bfloat16(v);
                __nv_bfloat16 lo = __float2bfloat16(v - __bfloat162float(hi));
                char* bp = sm + OFF_B + xn[m] * BST + (64 + xf[m]) * 2;
                *(__nv_bfloat16*)bp = hi;
                *(__nv_bfloat16*)(bp + BSECT) = lo;
            }
        }
    }

    // ---- roles: warp w -> units 16*(w&3)..+15 (all 4 gate groups), batches (w>>2)*8..+7
    const int wq = wid & 3;
    const int nb = (wid >> 2) * 8;
    const int r = lane >> 2;
    const int u0 = wq * 16 + r, u1 = u0 + 8;
    const int c0 = nb + 2 * (lane & 3), c1 = c0 + 1;

    float bias[8], w64r[8];
#pragma unroll
    for (int G = 0; G < 4; ++G) {
        int ga = G * 64 + u0, gb_ = G * 64 + u1;
        bias[G * 2] = bih[ga] + bhh[ga];
        bias[G * 2 + 1] = bih[gb_] + bhh[gb_];
        w64r[G * 2] = Wih[ga * 65 + 64];
        w64r[G * 2 + 1] = Wih[gb_ * 65 + 64];
    }
    float cst[4] = {0.f, 0.f, 0.f, 0.f};   // cells (u0,c0),(u0,c1),(u1,c0),(u1,c1)

    // ldmatrix base: + split-offset + G*64*AST + kt*32
    const u32 aBase = smb + (wq * 16 + (lane & 15)) * AST + (lane >> 4) * 16;
    // B frag base: row n = nb + lane/4, k-byte = (lane%4)*4 ; + par/split + kt*32 (b1 at +16)
    const u32 bBase = smb + OFF_B + (nb + (lane >> 2)) * BST + (lane & 3) * 4;

    __syncthreads();

    for (int t = 0; t < T_SZ; ++t) {
        const int par = t & 1, nxt = par ^ 1;
        const bool hasNext = (t + 1 < T_SZ);

        // ---- load B fragments (hx hi/lo) for this parity ----
        u32 bh[16], bl[16];
        {
            const char* ph = (const char*)sm + (bBase - smb) + par * 2 * BSECT;
#pragma unroll
            for (int kt = 0; kt < 8; ++kt) {
                bh[2 * kt]     = *(const u32*)(ph + kt * 32);
                bh[2 * kt + 1] = *(const u32*)(ph + kt * 32 + 16);
                bl[2 * kt]     = *(const u32*)(ph + BSECT + kt * 32);
                bl[2 * kt + 1] = *(const u32*)(ph + BSECT + kt * 32 + 16);
            }
        }
        // ---- prefetch x(t+1) ----
        float xv[5];
#pragma unroll
        for (int m = 0; m < 5; ++m) xv[m] = (hasNext && xok[m]) ? *xptr[m] : 0.f;
        // x64 for this step
        const float xs0 = ((float*)(sm + OFF_X64))[par * 16 + c0];
        const float xs1 = ((float*)(sm + OFF_X64))[par * 16 + c1];

        // ---- MMA: 4 gate groups x 8 k-tiles x 3 split products ----
        float D[4][4];
#pragma unroll
        for (int G = 0; G < 4; ++G) { D[G][0] = D[G][1] = D[G][2] = D[G][3] = 0.f; }
#pragma unroll
        for (int G = 0; G < 4; ++G) {
            const u32 ah_b = aBase + OFF_AH + G * 64 * AST;
            const u32 al_b = aBase + OFF_AL + G * 64 * AST;
#pragma unroll
            for (int kt = 0; kt < 8; ++kt) {
                u32 ah[4], al[4];
                ldsm4(ah[0], ah[1], ah[2], ah[3], ah_b + kt * 32);
                ldsm4(al[0], al[1], al[2], al[3], al_b + kt * 32);
                mma16816(D[G], ah, bh[2 * kt], bh[2 * kt + 1]);
                mma16816(D[G], ah, bl[2 * kt], bl[2 * kt + 1]);
                mma16816(D[G], al, bh[2 * kt], bh[2 * kt + 1]);
            }
        }

        // ---- update (in registers): cells q: 0=(u0,c0) 1=(u0,c1) 2=(u1,c0) 3=(u1,c1) ----
#pragma unroll
        for (int q = 0; q < 4; ++q) {
            const int uu = (q >> 1);              // 0: u0 rows, 1: u1 rows
            const float xs = (q & 1) ? xs1 : xs0;
            const int cc = (q & 1) ? c1 : c0;
            const int un = uu ? u1 : u0;
            // D fragment index: d0=(u0,c0) d1=(u0,c1) d2=(u1,c0) d3=(u1,c1) == q
            float gi = D[0][q] + fmaf(w64r[0 + uu], xs, bias[0 + uu]);
            float gf = D[1][q] + fmaf(w64r[2 + uu], xs, bias[2 + uu]);
            float gg = D[2][q] + fmaf(w64r[4 + uu], xs, bias[4 + uu]);
            float go = D[3][q] + fmaf(w64r[6 + uu], xs, bias[6 + uu]);
            float iv = sigf(gi), fv = sigf(gf), gv = tanhf_(gg), ov = sigf(go);
            cst[q] = fv * cst[q] + iv * gv;
            float h = ov * tanhf_(cst[q]);
            // h -> split bf16 into hx[nxt] (row = batch cc, col = unit un)
            __nv_bfloat16 hi = __float2bfloat16(h);
            __nv_bfloat16 lo = __float2bfloat16(h - __bfloat162float(hi));
            char* hp = sm + OFF_B + nxt * 2 * BSECT + cc * BST + un * 2;
            *(__nv_bfloat16*)hp = hi;
            *(__nv_bfloat16*)(hp + BSECT) = lo;
            if (t == T_SZ - 1) ((float*)(sm + OFF_HFIN))[cc * 68 + un] = h;
        }

        // ---- commit x(t+1) ----
        if (hasNext) {
#pragma unroll
            for (int m = 0; m < 5; ++m) {
                if (xok[m]) {
                    float v = xv[m];
                    xptr[m] += IN_SZ;
                    if (xf[m] == 64) ((float*)(sm + OFF_X64))[nxt * 16 + xn[m]] = v;
                    else {
                        __nv_bfloat16 hi = __float2bfloat16(v);
                        __nv_bfloat16 lo = __float2bfloat16(v - __bfloat162float(hi));
                        char* bp = sm + OFF_B + nxt * 2 * BSECT + xn[m] * BST + (64 + xf[m]) * 2;
                        *(__nv_bfloat16*)bp = hi;
                        *(__nv_bfloat16*)(bp + BSECT) = lo;
                    }
                }
            }
        }
        __syncthreads();
    }

    // ---- FC head ----
    if (tid < BR * 7) {
        int rr = tid / 7, o = tid - rr * 7;
        float s = fcb[o];
        const float* wrow = fcW + o * H_SZ;
        const float* hf = (const float*)(sm + OFF_HFIN) + rr * 68;
#pragma unroll 8
        for (int u = 0; u < H_SZ; ++u) s += wrow[u] * hf[u];
        out[(size_t)(b0 + rr) * 7 + o] = sigf(s);
    }
}

extern "C" void kernel_launch(void* const* d_in, const int* in_sizes, int n_in,
                              void* d_out, int out_size) {
    const float* x    = (const float*)d_in[0];
    const float* Wih  = (const float*)d_in[1];
    const float* Whh  = (const float*)d_in[2];
    const float* bih  = (const float*)d_in[3];
    const float* bhh  = (const float*)d_in[4];
    const float* fcW  = (const float*)d_in[5];
    const float* fcb  = (const float*)d_in[6];
    float* out = (float*)d_out;

    cudaFuncSetAttribute(lstm_mma_kernel,
                         cudaFuncAttributeMaxDynamicSharedMemorySize, SMEM_TOTAL);
    lstm_mma_kernel<<<B_SZ / BR, NTH, SMEM_TOTAL>>>(x, Wih, Whh, bih, bhh, fcW, fcb, out);
}